// round 13
// baseline (speedup 1.0000x reference)
#include <cuda_runtime.h>
#include <cuda_bf16.h>
#include <cuda_fp16.h>
#include <cstdint>

#define NN 100000
#define EE 3200000
#define DD 256
#define D4 64
#define SCB 391   // ceil(NN/256)

__device__ int   g_deg[NN];
__device__ int   g_off[NN + 1];
__device__ int   g_cur[NN];
__device__ int   g_srcs[EE];
__device__ int   g_part[SCB];
__device__ uint2 g_x16[(size_t)NN * D4];   // fp16 x (row = 64 uint2)
__device__ uint2 g_h16[(size_t)NN * D4];   // fp16 h
__device__ uint2 g_a16[(size_t)NN * D4];   // fp16 agg result

// ---------------- CSC build ----------------
__global__ void k_zero() {
    int i = blockIdx.x * blockDim.x + threadIdx.x;
    if (i < NN) { g_deg[i] = 0; g_cur[i] = 0; }
}

__global__ void k_deg(const int* __restrict__ ei) {
    int e = blockIdx.x * blockDim.x + threadIdx.x;
    if (e < EE) {
        int t = ei[EE + e];
        if (t >= 0 && t < NN) atomicAdd(&g_deg[t], 1);
    }
}

__global__ void __launch_bounds__(256) k_scan1() {
    __shared__ int sh[256];
    int i = blockIdx.x * 256 + threadIdx.x;
    sh[threadIdx.x] = (i < NN) ? g_deg[i] : 0;
    __syncthreads();
    for (int d = 128; d > 0; d >>= 1) {
        if (threadIdx.x < d) sh[threadIdx.x] += sh[threadIdx.x + d];
        __syncthreads();
    }
    if (threadIdx.x == 0) g_part[blockIdx.x] = sh[0];
}

__global__ void __launch_bounds__(512) k_scan2b() {
    __shared__ int sh[512];
    int tid = threadIdx.x;
    int own = (tid < SCB) ? g_part[tid] : 0;
    sh[tid] = own;
    __syncthreads();
    for (int d = 1; d < 512; d <<= 1) {
        int v = (tid >= d) ? sh[tid - d] : 0;
        __syncthreads();
        sh[tid] += v;
        __syncthreads();
    }
    if (tid < SCB) g_part[tid] = sh[tid] - own;
}

__global__ void __launch_bounds__(256) k_scan3() {
    __shared__ int sh[256];
    int i = blockIdx.x * 256 + threadIdx.x;
    int own = (i < NN) ? g_deg[i] : 0;
    sh[threadIdx.x] = own;
    __syncthreads();
    for (int d = 1; d < 256; d <<= 1) {
        int v = (threadIdx.x >= d) ? sh[threadIdx.x - d] : 0;
        __syncthreads();
        sh[threadIdx.x] += v;
        __syncthreads();
    }
    if (i < NN) g_off[i] = g_part[blockIdx.x] + sh[threadIdx.x] - own;
    if (i == NN - 1) g_off[NN] = EE;
}

__global__ void k_scatter(const int* __restrict__ ei) {
    int e = blockIdx.x * blockDim.x + threadIdx.x;
    if (e < EE) {
        int t = ei[EE + e];
        int s = ei[e];
        if (t >= 0 && t < NN && s >= 0 && s < NN) {
            int p = atomicAdd(&g_cur[t], 1);
            g_srcs[g_off[t] + p] = s;
        }
    }
}

// ---------------- fp32 -> fp16 conversion (x table) ----------------
__global__ void __launch_bounds__(256) k_cvt(const float4* __restrict__ in,
                                             uint2* __restrict__ out16) {
    int i = blockIdx.x * blockDim.x + threadIdx.x;
    if (i < NN * D4) {
        float4 a = in[i];
        __half2 h0 = __floats2half2_rn(a.x, a.y);
        __half2 h1 = __floats2half2_rn(a.z, a.w);
        uint2 o;
        o.x = *(unsigned*)&h0;
        o.y = *(unsigned*)&h1;
        out16[i] = o;
    }
}

// ---------------- mean aggregation: fp16 gather, fp32 accum, fp16 out ----------------
// 4 nodes/block x 64 lanes; lane owns 8B (4 halves); 4-edge unroll. (R8-proven loop)
__global__ void __launch_bounds__(256) k_agg16(const uint2* __restrict__ x16,
                                               uint2* __restrict__ out16) {
    int node = blockIdx.x * 4 + (threadIdx.x >> 6);
    int t = threadIdx.x & 63;
    if (node >= NN) return;
    int beg = g_off[node];
    int end = g_off[node + 1];

    float4 a = make_float4(0.f, 0.f, 0.f, 0.f);
    float4 b = make_float4(0.f, 0.f, 0.f, 0.f);
    int i = beg;
    for (; i + 4 <= end; i += 4) {
        int s0 = g_srcs[i];
        int s1 = g_srcs[i + 1];
        int s2 = g_srcs[i + 2];
        int s3 = g_srcs[i + 3];
        uint2 v0 = x16[(size_t)s0 * D4 + t];
        uint2 v1 = x16[(size_t)s1 * D4 + t];
        uint2 v2 = x16[(size_t)s2 * D4 + t];
        uint2 v3 = x16[(size_t)s3 * D4 + t];
        float2 f;
        f = __half22float2(*(__half2*)&v0.x); a.x += f.x; a.y += f.y;
        f = __half22float2(*(__half2*)&v0.y); a.z += f.x; a.w += f.y;
        f = __half22float2(*(__half2*)&v1.x); b.x += f.x; b.y += f.y;
        f = __half22float2(*(__half2*)&v1.y); b.z += f.x; b.w += f.y;
        f = __half22float2(*(__half2*)&v2.x); a.x += f.x; a.y += f.y;
        f = __half22float2(*(__half2*)&v2.y); a.z += f.x; a.w += f.y;
        f = __half22float2(*(__half2*)&v3.x); b.x += f.x; b.y += f.y;
        f = __half22float2(*(__half2*)&v3.y); b.z += f.x; b.w += f.y;
    }
    for (; i < end; i++) {
        uint2 v = x16[(size_t)g_srcs[i] * D4 + t];
        float2 f;
        f = __half22float2(*(__half2*)&v.x); a.x += f.x; a.y += f.y;
        f = __half22float2(*(__half2*)&v.y); a.z += f.x; a.w += f.y;
    }
    float inv = 1.0f / fmaxf((float)(end - beg), 1.0f);
    __half2 o0 = __floats2half2_rn((a.x + b.x) * inv, (a.y + b.y) * inv);
    __half2 o1 = __floats2half2_rn((a.z + b.z) * inv, (a.w + b.w) * inv);
    uint2 o;
    o.x = *(unsigned*)&o0;
    o.y = *(unsigned*)&o1;
    out16[(size_t)node * D4 + t] = o;
}

// ---------------- tensor-core fused dual GEMM (fp16 operands, register-safe loader) ----------------
// Grid (2, 782): x = column block, y = row block (L2 reuse of A/X between the 2 col blocks).
// A16/X16 fp16 -> split EXACTLY into bf16 hi+lo. Weights fp32 -> bf16 hi/lo.
#define BM 128
#define BN 128
#define BK 32
#define APAD 40
#define BPAD 136

__device__ __forceinline__ unsigned sptr(const void* p) {
    return (unsigned)__cvta_generic_to_shared(p);
}

__device__ __forceinline__ void ldm_x4(unsigned* r, unsigned addr) {
    asm volatile("ldmatrix.sync.aligned.m8n8.x4.shared.b16 {%0,%1,%2,%3}, [%4];"
                 : "=r"(r[0]), "=r"(r[1]), "=r"(r[2]), "=r"(r[3])
                 : "r"(addr));
}

__device__ __forceinline__ void ldm_x4t(unsigned* r, unsigned addr) {
    asm volatile("ldmatrix.sync.aligned.m8n8.x4.trans.shared.b16 {%0,%1,%2,%3}, [%4];"
                 : "=r"(r[0]), "=r"(r[1]), "=r"(r[2]), "=r"(r[3])
                 : "r"(addr));
}

__device__ __forceinline__ void mma_bf16(float* d, const unsigned* a, const unsigned* b) {
    asm volatile("mma.sync.aligned.m16n8k16.row.col.f32.bf16.bf16.f32 "
                 "{%0,%1,%2,%3}, {%4,%5,%6,%7}, {%8,%9}, {%0,%1,%2,%3};"
                 : "+f"(d[0]), "+f"(d[1]), "+f"(d[2]), "+f"(d[3])
                 : "r"(a[0]), "r"(a[1]), "r"(a[2]), "r"(a[3]),
                   "r"(b[0]), "r"(b[1]));
}

__device__ __forceinline__ void split2(float x, float y, unsigned* hi, unsigned* lo) {
    __nv_bfloat16 hx = __float2bfloat16(x);
    __nv_bfloat16 hy = __float2bfloat16(y);
    float lx = x - __bfloat162float(hx);
    float ly = y - __bfloat162float(hy);
    __nv_bfloat162 h2 = __halves2bfloat162(hx, hy);
    __nv_bfloat162 l2 = __halves2bfloat162(__float2bfloat16(lx), __float2bfloat16(ly));
    *hi = *(unsigned*)&h2;
    *lo = *(unsigned*)&l2;
}

__global__ void __launch_bounds__(256) k_gemm_tc(const __half* __restrict__ A16,
                                                 const __half* __restrict__ X16,
                                                 const float* __restrict__ W1,
                                                 const float* __restrict__ W2,
                                                 const float* __restrict__ bias,
                                                 float* __restrict__ O32,
                                                 __half* __restrict__ O16,
                                                 int do_relu) {
    __shared__ __nv_bfloat16 Ah[BM][APAD];
    __shared__ __nv_bfloat16 Al[BM][APAD];
    __shared__ __nv_bfloat16 Bh[BK][BPAD];
    __shared__ __nv_bfloat16 Bl[BK][BPAD];

    int tid = threadIdx.x;
    int wid = tid >> 5;
    int lane = tid & 31;
    int warp_m = wid >> 1;
    int warp_n = wid & 1;
    int row0 = blockIdx.y * BM;
    int col0 = blockIdx.x * BN;

    float acc[2][8][4];
    for (int i = 0; i < 2; i++) {
        for (int j = 0; j < 8; j++) {
            for (int q = 0; q < 4; q++) {
                acc[i][j][q] = 0.f;
            }
        }
    }

    int ar = tid >> 1;
    int ac = (tid & 1) * 16;
    int br = tid >> 3;
    int bc = (tid & 7) * 16;

    for (int phase = 0; phase < 2; phase++) {
        const __half* Ain = phase ? X16 : A16;
        const float* Win = phase ? W2 : W1;

        for (int kt = 0; kt < DD; kt += BK) {
            // A tile loader: one uint2 (4 halves) per q iter -> same live-set as fp32 version
            int gr = row0 + ar;
            const __half* asrc = Ain + (size_t)gr * DD + kt + ac;
            for (int q = 0; q < 4; q++) {
                uint2 v = make_uint2(0u, 0u);
                if (gr < NN) v = *(const uint2*)(asrc + q * 4);
                float2 f0 = __half22float2(*(__half2*)&v.x);
                float2 f1 = __half22float2(*(__half2*)&v.y);
                unsigned h01, l01, h23, l23;
                split2(f0.x, f0.y, &h01, &l01);
                split2(f1.x, f1.y, &h23, &l23);
                int c = ac + q * 4;
                *(unsigned*)&Ah[ar][c]     = h01;
                *(unsigned*)&Ah[ar][c + 2] = h23;
                *(unsigned*)&Al[ar][c]     = l01;
                *(unsigned*)&Al[ar][c + 2] = l23;
            }
            // B tile (weights, fp32)
            const float* bsrc = Win + (size_t)(kt + br) * DD + col0 + bc;
            for (int q = 0; q < 4; q++) {
                float4 v = *(const float4*)(bsrc + q * 4);
                unsigned h01, l01, h23, l23;
                split2(v.x, v.y, &h01, &l01);
                split2(v.z, v.w, &h23, &l23);
                int c = bc + q * 4;
                *(unsigned*)&Bh[br][c]     = h01;
                *(unsigned*)&Bh[br][c + 2] = h23;
                *(unsigned*)&Bl[br][c]     = l01;
                *(unsigned*)&Bl[br][c + 2] = l23;
            }
            __syncthreads();

            for (int ks = 0; ks < BK; ks += 16) {
                unsigned ah[2][4];
                unsigned al[2][4];
                for (int i = 0; i < 2; i++) {
                    int r = warp_m * 32 + i * 16 + (lane & 15);
                    int c = ks + ((lane >> 4) << 3);
                    ldm_x4(ah[i], sptr(&Ah[r][c]));
                    ldm_x4(al[i], sptr(&Al[r][c]));
                }
                unsigned bh[8][2];
                unsigned bl[8][2];
                for (int j2 = 0; j2 < 4; j2++) {
                    int r = ks + (lane & 15);
                    int c = warp_n * 64 + j2 * 16 + ((lane >> 4) << 3);
                    unsigned t4[4];
                    ldm_x4t(t4, sptr(&Bh[r][c]));
                    bh[j2 * 2][0]     = t4[0];
                    bh[j2 * 2][1]     = t4[1];
                    bh[j2 * 2 + 1][0] = t4[2];
                    bh[j2 * 2 + 1][1] = t4[3];
                    ldm_x4t(t4, sptr(&Bl[r][c]));
                    bl[j2 * 2][0]     = t4[0];
                    bl[j2 * 2][1]     = t4[1];
                    bl[j2 * 2 + 1][0] = t4[2];
                    bl[j2 * 2 + 1][1] = t4[3];
                }
                for (int i = 0; i < 2; i++) {
                    for (int j = 0; j < 8; j++) {
                        mma_bf16(acc[i][j], ah[i], bh[j]);
                        mma_bf16(acc[i][j], ah[i], bl[j]);
                        mma_bf16(acc[i][j], al[i], bh[j]);
                    }
                }
            }
            __syncthreads();
        }
    }

    for (int j = 0; j < 8; j++) {
        int c = col0 + warp_n * 64 + j * 8 + (lane & 3) * 2;
        float2 bb = *(const float2*)(bias + c);
        for (int i = 0; i < 2; i++) {
            int r = row0 + warp_m * 32 + i * 16 + (lane >> 2);
            float v0 = acc[i][j][0] + bb.x;
            float v1 = acc[i][j][1] + bb.y;
            float v2 = acc[i][j][2] + bb.x;
            float v3 = acc[i][j][3] + bb.y;
            if (do_relu) {
                v0 = fmaxf(v0, 0.f);
                v1 = fmaxf(v1, 0.f);
                v2 = fmaxf(v2, 0.f);
                v3 = fmaxf(v3, 0.f);
            }
            if (r < NN) {
                if (O32) *(float2*)(O32 + (size_t)r * DD + c) = make_float2(v0, v1);
                if (O16) {
                    __half2 hh = __floats2half2_rn(v0, v1);
                    *(__half2*)(O16 + (size_t)r * DD + c) = hh;
                }
            }
            if (r + 8 < NN) {
                if (O32) *(float2*)(O32 + (size_t)(r + 8) * DD + c) = make_float2(v2, v3);
                if (O16) {
                    __half2 hh = __floats2half2_rn(v2, v3);
                    *(__half2*)(O16 + (size_t)(r + 8) * DD + c) = hh;
                }
            }
        }
    }
}

extern "C" void kernel_launch(void* const* d_in, const int* in_sizes, int n_in,
                              void* d_out, int out_size) {
    const float* x   = (const float*)d_in[0];
    const int*   ei  = (const int*)d_in[1];
    const float* Wl1 = (const float*)d_in[2];
    const float* b1  = (const float*)d_in[3];
    const float* Wr1 = (const float*)d_in[4];
    const float* Wl2 = (const float*)d_in[5];
    const float* b2  = (const float*)d_in[6];
    const float* Wr2 = (const float*)d_in[7];
    float*       out = (float*)d_out;

    void* x16_p = 0;
    void* h16_p = 0;
    void* a16_p = 0;
    cudaGetSymbolAddress(&x16_p, g_x16);
    cudaGetSymbolAddress(&h16_p, g_h16);
    cudaGetSymbolAddress(&a16_p, g_a16);
    uint2* x16 = (uint2*)x16_p;
    uint2* h16 = (uint2*)h16_p;
    uint2* a16 = (uint2*)a16_p;

    k_zero<<<(NN + 255) / 256, 256>>>();
    k_deg<<<(EE + 255) / 256, 256>>>(ei);
    k_cvt<<<(NN * D4 + 255) / 256, 256>>>((const float4*)x, x16);
    k_scan1<<<SCB, 256>>>();
    k_scan2b<<<1, 512>>>();
    k_scan3<<<SCB, 256>>>();
    k_scatter<<<(EE + 255) / 256, 256>>>(ei);

    dim3 ggrid(DD / BN, (NN + BM - 1) / BM);   // (2, 782): x=cols, y=rows

    // layer 1: agg(x16) -> a16; gemm(A=a16, X=x16) -> h16 (fp16, +relu)
    k_agg16<<<(NN + 3) / 4, 256>>>(x16, a16);
    k_gemm_tc<<<ggrid, 256>>>((const __half*)a16, (const __half*)x16, Wl1, Wr1, b1,
                              (float*)0, (__half*)h16, 1);

    // layer 2: agg(h16) -> a16; gemm(A=a16, X=h16) -> out (fp32)
    k_agg16<<<(NN + 3) / 4, 256>>>(h16, a16);
    k_gemm_tc<<<ggrid, 256>>>((const __half*)a16, (const __half*)h16, Wl2, Wr2, b2,
                              out, (__half*)0, 0);
}

// round 14
// speedup vs baseline: 1.1918x; 1.1918x over previous
#include <cuda_runtime.h>
#include <cuda_bf16.h>
#include <cuda_fp16.h>
#include <cstdint>

#define NN 100000
#define EE 3200000
#define DD 256
#define D4 64
#define SCB 391   // ceil(NN/256)

__device__ int    g_deg[NN];
__device__ int    g_off[NN + 1];
__device__ int    g_cur[NN];
__device__ int    g_srcs[EE];
__device__ int    g_part[SCB];
__device__ float4 g_agg4[(size_t)NN * D4];
__device__ float4 g_h4[(size_t)NN * D4];
__device__ uint2  g_x16[(size_t)NN * D4];   // fp16 x (row = 64 uint2)
__device__ uint2  g_h16[(size_t)NN * D4];   // fp16 h

// ---------------- CSC build ----------------
__global__ void k_zero() {
    int i = blockIdx.x * blockDim.x + threadIdx.x;
    if (i < NN) { g_deg[i] = 0; g_cur[i] = 0; }
}

// fused: convert x -> fp16 (6.4M threads) AND degree histogram (first 3.2M threads)
__global__ void __launch_bounds__(256) k_deg_cvt(const int* __restrict__ ei,
                                                 const float4* __restrict__ in,
                                                 uint2* __restrict__ out16) {
    int i = blockIdx.x * blockDim.x + threadIdx.x;
    if (i < NN * D4) {
        float4 a = in[i];
        __half2 h0 = __floats2half2_rn(a.x, a.y);
        __half2 h1 = __floats2half2_rn(a.z, a.w);
        uint2 o;
        o.x = *(unsigned*)&h0;
        o.y = *(unsigned*)&h1;
        out16[i] = o;
    }
    if (i < EE) {
        int t = ei[EE + i];
        if (t >= 0 && t < NN) atomicAdd(&g_deg[t], 1);
    }
}

__global__ void __launch_bounds__(256) k_scan1() {
    __shared__ int sh[256];
    int i = blockIdx.x * 256 + threadIdx.x;
    sh[threadIdx.x] = (i < NN) ? g_deg[i] : 0;
    __syncthreads();
    for (int d = 128; d > 0; d >>= 1) {
        if (threadIdx.x < d) sh[threadIdx.x] += sh[threadIdx.x + d];
        __syncthreads();
    }
    if (threadIdx.x == 0) g_part[blockIdx.x] = sh[0];
}

__global__ void __launch_bounds__(512) k_scan2b() {
    __shared__ int sh[512];
    int tid = threadIdx.x;
    int own = (tid < SCB) ? g_part[tid] : 0;
    sh[tid] = own;
    __syncthreads();
    for (int d = 1; d < 512; d <<= 1) {
        int v = (tid >= d) ? sh[tid - d] : 0;
        __syncthreads();
        sh[tid] += v;
        __syncthreads();
    }
    if (tid < SCB) g_part[tid] = sh[tid] - own;
}

__global__ void __launch_bounds__(256) k_scan3() {
    __shared__ int sh[256];
    int i = blockIdx.x * 256 + threadIdx.x;
    int own = (i < NN) ? g_deg[i] : 0;
    sh[threadIdx.x] = own;
    __syncthreads();
    for (int d = 1; d < 256; d <<= 1) {
        int v = (threadIdx.x >= d) ? sh[threadIdx.x - d] : 0;
        __syncthreads();
        sh[threadIdx.x] += v;
        __syncthreads();
    }
    if (i < NN) g_off[i] = g_part[blockIdx.x] + sh[threadIdx.x] - own;
    if (i == NN - 1) g_off[NN] = EE;
}

__global__ void k_scatter(const int* __restrict__ ei) {
    int e = blockIdx.x * blockDim.x + threadIdx.x;
    if (e < EE) {
        int t = ei[EE + e];
        int s = ei[e];
        if (t >= 0 && t < NN && s >= 0 && s < NN) {
            int p = atomicAdd(&g_cur[t], 1);
            g_srcs[g_off[t] + p] = s;
        }
    }
}

// ---------------- mean aggregation: fp16 gather, fp32 accum/out, 8-edge unroll ----------------
// 4 nodes/block x 64 lanes; lane owns 8B (4 halves) of the 512B row.
__global__ void __launch_bounds__(256) k_agg16(const uint2* __restrict__ x16,
                                               float4* __restrict__ out4) {
    int node = blockIdx.x * 4 + (threadIdx.x >> 6);
    int t = threadIdx.x & 63;
    if (node >= NN) return;
    int beg = g_off[node];
    int end = g_off[node + 1];

    float4 a = make_float4(0.f, 0.f, 0.f, 0.f);
    float4 b = make_float4(0.f, 0.f, 0.f, 0.f);
    int i = beg;
    for (; i + 8 <= end; i += 8) {
        uint2 v0 = x16[(size_t)g_srcs[i]     * D4 + t];
        uint2 v1 = x16[(size_t)g_srcs[i + 1] * D4 + t];
        uint2 v2 = x16[(size_t)g_srcs[i + 2] * D4 + t];
        uint2 v3 = x16[(size_t)g_srcs[i + 3] * D4 + t];
        uint2 v4 = x16[(size_t)g_srcs[i + 4] * D4 + t];
        uint2 v5 = x16[(size_t)g_srcs[i + 5] * D4 + t];
        uint2 v6 = x16[(size_t)g_srcs[i + 6] * D4 + t];
        uint2 v7 = x16[(size_t)g_srcs[i + 7] * D4 + t];
        float2 f;
        f = __half22float2(*(__half2*)&v0.x); a.x += f.x; a.y += f.y;
        f = __half22float2(*(__half2*)&v0.y); a.z += f.x; a.w += f.y;
        f = __half22float2(*(__half2*)&v1.x); b.x += f.x; b.y += f.y;
        f = __half22float2(*(__half2*)&v1.y); b.z += f.x; b.w += f.y;
        f = __half22float2(*(__half2*)&v2.x); a.x += f.x; a.y += f.y;
        f = __half22float2(*(__half2*)&v2.y); a.z += f.x; a.w += f.y;
        f = __half22float2(*(__half2*)&v3.x); b.x += f.x; b.y += f.y;
        f = __half22float2(*(__half2*)&v3.y); b.z += f.x; b.w += f.y;
        f = __half22float2(*(__half2*)&v4.x); a.x += f.x; a.y += f.y;
        f = __half22float2(*(__half2*)&v4.y); a.z += f.x; a.w += f.y;
        f = __half22float2(*(__half2*)&v5.x); b.x += f.x; b.y += f.y;
        f = __half22float2(*(__half2*)&v5.y); b.z += f.x; b.w += f.y;
        f = __half22float2(*(__half2*)&v6.x); a.x += f.x; a.y += f.y;
        f = __half22float2(*(__half2*)&v6.y); a.z += f.x; a.w += f.y;
        f = __half22float2(*(__half2*)&v7.x); b.x += f.x; b.y += f.y;
        f = __half22float2(*(__half2*)&v7.y); b.z += f.x; b.w += f.y;
    }
    for (; i < end; i++) {
        uint2 v = x16[(size_t)g_srcs[i] * D4 + t];
        float2 f;
        f = __half22float2(*(__half2*)&v.x); a.x += f.x; a.y += f.y;
        f = __half22float2(*(__half2*)&v.y); a.z += f.x; a.w += f.y;
    }
    float inv = 1.0f / fmaxf((float)(end - beg), 1.0f);
    float4 r;
    r.x = (a.x + b.x) * inv;
    r.y = (a.y + b.y) * inv;
    r.z = (a.z + b.z) * inv;
    r.w = (a.w + b.w) * inv;
    out4[(size_t)node * D4 + t] = r;
}

// ---------------- tensor-core fused dual GEMM (R12-proven: fp32 operands, grid-swapped) ----------------
#define BM 128
#define BN 128
#define BK 32
#define APAD 40
#define BPAD 136

__device__ __forceinline__ unsigned sptr(const void* p) {
    return (unsigned)__cvta_generic_to_shared(p);
}

__device__ __forceinline__ void ldm_x4(unsigned* r, unsigned addr) {
    asm volatile("ldmatrix.sync.aligned.m8n8.x4.shared.b16 {%0,%1,%2,%3}, [%4];"
                 : "=r"(r[0]), "=r"(r[1]), "=r"(r[2]), "=r"(r[3])
                 : "r"(addr));
}

__device__ __forceinline__ void ldm_x4t(unsigned* r, unsigned addr) {
    asm volatile("ldmatrix.sync.aligned.m8n8.x4.trans.shared.b16 {%0,%1,%2,%3}, [%4];"
                 : "=r"(r[0]), "=r"(r[1]), "=r"(r[2]), "=r"(r[3])
                 : "r"(addr));
}

__device__ __forceinline__ void mma_bf16(float* d, const unsigned* a, const unsigned* b) {
    asm volatile("mma.sync.aligned.m16n8k16.row.col.f32.bf16.bf16.f32 "
                 "{%0,%1,%2,%3}, {%4,%5,%6,%7}, {%8,%9}, {%0,%1,%2,%3};"
                 : "+f"(d[0]), "+f"(d[1]), "+f"(d[2]), "+f"(d[3])
                 : "r"(a[0]), "r"(a[1]), "r"(a[2]), "r"(a[3]),
                   "r"(b[0]), "r"(b[1]));
}

__device__ __forceinline__ void split2(float x, float y, unsigned* hi, unsigned* lo) {
    __nv_bfloat16 hx = __float2bfloat16(x);
    __nv_bfloat16 hy = __float2bfloat16(y);
    float lx = x - __bfloat162float(hx);
    float ly = y - __bfloat162float(hy);
    __nv_bfloat162 h2 = __halves2bfloat162(hx, hy);
    __nv_bfloat162 l2 = __halves2bfloat162(__float2bfloat16(lx), __float2bfloat16(ly));
    *hi = *(unsigned*)&h2;
    *lo = *(unsigned*)&l2;
}

__global__ void __launch_bounds__(256) k_gemm_tc(const float* __restrict__ A,
                                                 const float* __restrict__ X,
                                                 const float* __restrict__ W1,
                                                 const float* __restrict__ W2,
                                                 const float* __restrict__ bias,
                                                 float* __restrict__ O,
                                                 __half* __restrict__ O16,
                                                 int do_relu) {
    __shared__ __nv_bfloat16 Ah[BM][APAD];
    __shared__ __nv_bfloat16 Al[BM][APAD];
    __shared__ __nv_bfloat16 Bh[BK][BPAD];
    __shared__ __nv_bfloat16 Bl[BK][BPAD];

    int tid = threadIdx.x;
    int wid = tid >> 5;
    int lane = tid & 31;
    int warp_m = wid >> 1;
    int warp_n = wid & 1;
    int row0 = blockIdx.y * BM;   // y = row block
    int col0 = blockIdx.x * BN;   // x = column block (L2 reuse between the 2 col blocks)

    float acc[2][8][4];
    for (int i = 0; i < 2; i++) {
        for (int j = 0; j < 8; j++) {
            for (int q = 0; q < 4; q++) {
                acc[i][j][q] = 0.f;
            }
        }
    }

    int ar = tid >> 1;
    int ac = (tid & 1) * 16;
    int br = tid >> 3;
    int bc = (tid & 7) * 16;

    for (int phase = 0; phase < 2; phase++) {
        const float* Ain = phase ? X : A;
        const float* Win = phase ? W2 : W1;

        for (int kt = 0; kt < DD; kt += BK) {
            int gr = row0 + ar;
            const float* asrc = Ain + (size_t)gr * DD + kt + ac;
            for (int q = 0; q < 4; q++) {
                float4 v = make_float4(0.f, 0.f, 0.f, 0.f);
                if (gr < NN) v = *(const float4*)(asrc + q * 4);
                unsigned h01, l01, h23, l23;
                split2(v.x, v.y, &h01, &l01);
                split2(v.z, v.w, &h23, &l23);
                int c = ac + q * 4;
                *(unsigned*)&Ah[ar][c]     = h01;
                *(unsigned*)&Ah[ar][c + 2] = h23;
                *(unsigned*)&Al[ar][c]     = l01;
                *(unsigned*)&Al[ar][c + 2] = l23;
            }
            const float* bsrc = Win + (size_t)(kt + br) * DD + col0 + bc;
            for (int q = 0; q < 4; q++) {
                float4 v = *(const float4*)(bsrc + q * 4);
                unsigned h01, l01, h23, l23;
                split2(v.x, v.y, &h01, &l01);
                split2(v.z, v.w, &h23, &l23);
                int c = bc + q * 4;
                *(unsigned*)&Bh[br][c]     = h01;
                *(unsigned*)&Bh[br][c + 2] = h23;
                *(unsigned*)&Bl[br][c]     = l01;
                *(unsigned*)&Bl[br][c + 2] = l23;
            }
            __syncthreads();

            for (int ks = 0; ks < BK; ks += 16) {
                unsigned ah[2][4];
                unsigned al[2][4];
                for (int i = 0; i < 2; i++) {
                    int r = warp_m * 32 + i * 16 + (lane & 15);
                    int c = ks + ((lane >> 4) << 3);
                    ldm_x4(ah[i], sptr(&Ah[r][c]));
                    ldm_x4(al[i], sptr(&Al[r][c]));
                }
                unsigned bh[8][2];
                unsigned bl[8][2];
                for (int j2 = 0; j2 < 4; j2++) {
                    int r = ks + (lane & 15);
                    int c = warp_n * 64 + j2 * 16 + ((lane >> 4) << 3);
                    unsigned t4[4];
                    ldm_x4t(t4, sptr(&Bh[r][c]));
                    bh[j2 * 2][0]     = t4[0];
                    bh[j2 * 2][1]     = t4[1];
                    bh[j2 * 2 + 1][0] = t4[2];
                    bh[j2 * 2 + 1][1] = t4[3];
                    ldm_x4t(t4, sptr(&Bl[r][c]));
                    bl[j2 * 2][0]     = t4[0];
                    bl[j2 * 2][1]     = t4[1];
                    bl[j2 * 2 + 1][0] = t4[2];
                    bl[j2 * 2 + 1][1] = t4[3];
                }
                for (int i = 0; i < 2; i++) {
                    for (int j = 0; j < 8; j++) {
                        mma_bf16(acc[i][j], ah[i], bh[j]);
                        mma_bf16(acc[i][j], ah[i], bl[j]);
                        mma_bf16(acc[i][j], al[i], bh[j]);
                    }
                }
            }
            __syncthreads();
        }
    }

    for (int j = 0; j < 8; j++) {
        int c = col0 + warp_n * 64 + j * 8 + (lane & 3) * 2;
        float2 bb = *(const float2*)(bias + c);
        for (int i = 0; i < 2; i++) {
            int r = row0 + warp_m * 32 + i * 16 + (lane >> 2);
            float v0 = acc[i][j][0] + bb.x;
            float v1 = acc[i][j][1] + bb.y;
            float v2 = acc[i][j][2] + bb.x;
            float v3 = acc[i][j][3] + bb.y;
            if (do_relu) {
                v0 = fmaxf(v0, 0.f);
                v1 = fmaxf(v1, 0.f);
                v2 = fmaxf(v2, 0.f);
                v3 = fmaxf(v3, 0.f);
            }
            if (r < NN) {
                *(float2*)(O + (size_t)r * DD + c) = make_float2(v0, v1);
                if (O16) {
                    __half2 hh = __floats2half2_rn(v0, v1);
                    *(__half2*)(O16 + (size_t)r * DD + c) = hh;
                }
            }
            if (r + 8 < NN) {
                *(float2*)(O + (size_t)(r + 8) * DD + c) = make_float2(v2, v3);
                if (O16) {
                    __half2 hh = __floats2half2_rn(v2, v3);
                    *(__half2*)(O16 + (size_t)(r + 8) * DD + c) = hh;
                }
            }
        }
    }
}

extern "C" void kernel_launch(void* const* d_in, const int* in_sizes, int n_in,
                              void* d_out, int out_size) {
    const float* x   = (const float*)d_in[0];
    const int*   ei  = (const int*)d_in[1];
    const float* Wl1 = (const float*)d_in[2];
    const float* b1  = (const float*)d_in[3];
    const float* Wr1 = (const float*)d_in[4];
    const float* Wl2 = (const float*)d_in[5];
    const float* b2  = (const float*)d_in[6];
    const float* Wr2 = (const float*)d_in[7];
    float*       out = (float*)d_out;

    void* agg_p = 0;
    void* h_p = 0;
    void* x16_p = 0;
    void* h16_p = 0;
    cudaGetSymbolAddress(&agg_p, g_agg4);
    cudaGetSymbolAddress(&h_p, g_h4);
    cudaGetSymbolAddress(&x16_p, g_x16);
    cudaGetSymbolAddress(&h16_p, g_h16);
    float4* agg4 = (float4*)agg_p;
    float4* h4   = (float4*)h_p;
    uint2*  x16  = (uint2*)x16_p;
    uint2*  h16  = (uint2*)h16_p;

    k_zero<<<(NN + 255) / 256, 256>>>();
    k_deg_cvt<<<(NN * D4 + 255) / 256, 256>>>(ei, (const float4*)x, x16);
    k_scan1<<<SCB, 256>>>();
    k_scan2b<<<1, 512>>>();
    k_scan3<<<SCB, 256>>>();
    k_scatter<<<(EE + 255) / 256, 256>>>(ei);

    dim3 ggrid(DD / BN, (NN + BM - 1) / BM);   // (2, 782): x=cols, y=rows

    // layer 1: agg(x16) -> agg4 (fp32); gemm(A=agg4, X=x) -> h4 + h16 mirror (+relu)
    k_agg16<<<(NN + 3) / 4, 256>>>(x16, agg4);
    k_gemm_tc<<<ggrid, 256>>>((const float*)agg4, x, Wl1, Wr1, b1,
                              (float*)h4, (__half*)h16, 1);

    // layer 2: agg(h16) -> agg4; gemm(A=agg4, X=h4) -> out
    k_agg16<<<(NN + 3) / 4, 256>>>(h16, agg4);
    k_gemm_tc<<<ggrid, 256>>>((const float*)agg4, (const float*)h4, Wl2, Wr2, b2,
                              out, (__half*)0, 0);
}